// round 15
// baseline (speedup 1.0000x reference)
#include <cuda_runtime.h>
#include <cuda_fp16.h>
#include <cstdint>

// Problem dims (fixed by setup_inputs)
#define BATCH 4
#define NG 64
#define NH 8
#define NP 4096
#define TILE 16
#define PITEM 64              // points per work item (4 tiles = 2 dual-tile passes)
#define NITEMS 2048           // 4 b * 8 gchunks * 64 pchunks
#define PBLKS 296             // 148 SMs * 2 blocks -> one full wave

struct __align__(16) Smem {
    uint4  Bp[8][4][32];      // W2' frags, nb-paired                      16 KB
    uint4  W1p[8][32];        // W1' frags {h0,l0,h1,l1}                    4 KB
    float4 sp[2][PITEM];      // scene points, double-buffered              2 KB
    uint4  bDp[4][32];        // stage-D A3 frags {h0,h1,l0,l1}             2 KB
    uint2  GEp[8][4];         // {G, EB} fp16x2 per (nb, t)                256 B
};                             // ~24.3 KB total

// fp16 split: hi + residual lo, packed fp16x2 (x0 low).
__device__ __forceinline__ void split2h(float x0, float x1, unsigned& hi, unsigned& lo) {
    asm("cvt.rn.f16x2.f32 %0, %1, %2;" : "=r"(hi) : "f"(x1), "f"(x0));
    __half2 hv = *reinterpret_cast<__half2*>(&hi);
    float2 back = __half22float2(hv);
    asm("cvt.rn.f16x2.f32 %0, %1, %2;" : "=r"(lo) : "f"(x1 - back.y), "f"(x0 - back.x));
}
__device__ __forceinline__ unsigned pack_h2(float x0, float x1) {
    unsigned u;
    asm("cvt.rn.f16x2.f32 %0, %1, %2;" : "=r"(u) : "f"(x1), "f"(x0));
    return u;
}
__device__ __forceinline__ float2 unpack_h2(unsigned u) {
    return __half22float2(*reinterpret_cast<__half2*>(&u));
}
__device__ __forceinline__ void mma_f16(float d[4], const unsigned a[4],
                                        unsigned b0, unsigned b1) {
    asm volatile(
        "mma.sync.aligned.m16n8k16.row.col.f32.f16.f16.f32 "
        "{%0,%1,%2,%3},{%4,%5,%6,%7},{%8,%9},{%0,%1,%2,%3};"
        : "+f"(d[0]), "+f"(d[1]), "+f"(d[2]), "+f"(d[3])
        : "r"(a[0]), "r"(a[1]), "r"(a[2]), "r"(a[3]), "r"(b0), "r"(b1));
}

__global__ void __launch_bounds__(256, 2)
gab_kernel(const float* __restrict__ scene,   // (B, NP, 3)
           const float* __restrict__ poses,   // (B, NG, 7)
           const float* __restrict__ W1, const float* __restrict__ b1,
           const float* __restrict__ g1, const float* __restrict__ be1,
           const float* __restrict__ W2, const float* __restrict__ b2,
           const float* __restrict__ g2, const float* __restrict__ be2,
           const float* __restrict__ W3, const float* __restrict__ b3,
           const float* __restrict__ bscale,
           float* __restrict__ out)            // (B, NH, NG, NP)
{
    extern __shared__ __align__(16) char smraw[];
    Smem& sm = *reinterpret_cast<Smem*>(smraw);

    const int tid = threadIdx.x;

    // ---- Once-per-block prologue (all g-independent) ----
    for (int idx = tid; idx < 8 * 4 * 32; idx += 256) {
        int kb = idx >> 7, rem = idx & 127;
        int nbp = rem >> 5, ln = rem & 31;
        int tt = ln & 3, c = ln >> 2;
        int n0 = (2 * nbp) * 8 + c, n1 = (2 * nbp + 1) * 8 + c;
        int k0 = kb * 16 + 2 * tt;
        float g0 = g1[k0 + 0], g1v = g1[k0 + 1], g8 = g1[k0 + 8], g9 = g1[k0 + 9];
        unsigned x = pack_h2(g0 * W2[(k0 + 0) * 64 + n0], g1v * W2[(k0 + 1) * 64 + n0]);
        unsigned y = pack_h2(g8 * W2[(k0 + 8) * 64 + n0], g9 * W2[(k0 + 9) * 64 + n0]);
        unsigned z = pack_h2(g0 * W2[(k0 + 0) * 64 + n1], g1v * W2[(k0 + 1) * 64 + n1]);
        unsigned w = pack_h2(g8 * W2[(k0 + 8) * 64 + n1], g9 * W2[(k0 + 9) * 64 + n1]);
        sm.Bp[kb][nbp][ln] = make_uint4(x, y, z, w);
    }
    for (int idx = tid; idx < 8 * 32; idx += 256) {
        int kbp = idx >> 5, ln = idx & 31;
        int tt = ln & 3, c = ln >> 2;
        int k0 = 2 * tt, k1 = 2 * tt + 1;
        int n0 = (2 * kbp) * 8 + c, n1 = (2 * kbp + 1) * 8 + c;
        // W1' rows: 0-3 = W1, 4 = b1, 5-7 = 0
        float w00 = (k0 < 4) ? W1[k0 * 128 + n0] : (k0 == 4 ? b1[n0] : 0.f);
        float w01 = (k1 < 4) ? W1[k1 * 128 + n0] : (k1 == 4 ? b1[n0] : 0.f);
        float w10 = (k0 < 4) ? W1[k0 * 128 + n1] : (k0 == 4 ? b1[n1] : 0.f);
        float w11 = (k1 < 4) ? W1[k1 * 128 + n1] : (k1 == 4 ? b1[n1] : 0.f);
        unsigned h0, l0, h1, l1;
        split2h(w00, w01, h0, l0);
        split2h(w10, w11, h1, l1);
        sm.W1p[kbp][ln] = make_uint4(h0, l0, h1, l1);
    }
    if (tid < 128) {      // stage-D A3 fragments
        int kb2 = tid >> 5, ln = tid & 31;
        int tt = ln & 3, gg2 = ln >> 2;
        int k0 = kb2 * 16 + 2 * tt;
        float a0 = g2[k0 + 0] * W3[(k0 + 0) * 8 + gg2];
        float a1 = g2[k0 + 1] * W3[(k0 + 1) * 8 + gg2];
        float a2 = g2[k0 + 8] * W3[(k0 + 8) * 8 + gg2];
        float a3 = g2[k0 + 9] * W3[(k0 + 9) * 8 + gg2];
        unsigned h0, l0, h1, l1;
        split2h(a0, a1, h0, l0);
        split2h(a2, a3, h1, l1);
        sm.bDp[kb2][ln] = make_uint4(h0, h1, l0, l1);
    }
    if (tid >= 128 && tid < 160) {   // G/EB fold vectors
        int j = tid - 128;
        int nb = j >> 2, tt = j & 3;
        int n0 = nb * 8 + 2 * tt, n1 = n0 + 1;
        float G0 = 0.f, G1 = 0.f, E0 = 0.f, E1 = 0.f;
        #pragma unroll 4
        for (int k = 0; k < 128; ++k) {
            float gk = g1[k], bk = be1[k];
            float w0 = W2[k * 64 + n0], w1 = W2[k * 64 + n1];
            G0 = fmaf(gk, w0, G0); G1 = fmaf(gk, w1, G1);
            E0 = fmaf(bk, w0, E0); E1 = fmaf(bk, w1, E1);
        }
        sm.GEp[nb][tt] = make_uint2(pack_h2(G0, G1),
                                    pack_h2(E0 + b2[n0], E1 + b2[n1]));
    }
    // Stage first item's scene chunk into buffer 0
    {
        int item0 = blockIdx.x;
        if (item0 < NITEMS && tid < PITEM) {
            int bb = item0 >> 9;
            int p0 = (item0 & 63) << 6;
            const float* spp = scene + ((size_t)bb * NP + p0 + tid) * 3;
            sm.sp[0][tid] = make_float4(spp[0], spp[1], spp[2], 0.f);
        }
    }
    __syncthreads();

    const int wid = tid >> 5, lane = tid & 31;
    const int t = lane & 3, gg = lane >> 2;   // mma fragment coords

    // ---- Per-head fold constants for heads h0 = 2t, h1 = 2t+1 (g-independent) ----
    float K2a = 0.f, K2b = 0.f, K1a = 0.f, K1b = 0.f;
    #pragma unroll 8
    for (int c = 0; c < 64; ++c) {
        float2 w = *reinterpret_cast<const float2*>(W3 + c * 8 + 2 * t);
        float gc = __ldg(g2 + c), bc = __ldg(be2 + c);
        K2a = fmaf(gc, w.x, K2a); K2b = fmaf(gc, w.y, K2b);
        K1a = fmaf(bc, w.x, K1a); K1b = fmaf(bc, w.y, K1b);
    }
    const float bsa = __ldg(bscale + 2 * t), bsb = __ldg(bscale + 2 * t + 1);
    const float C0a = (K1a + __ldg(b3 + 2 * t)) * bsa;
    const float C0b = (K1b + __ldg(b3 + 2 * t + 1)) * bsb;

    // ---- Persistent item loop: static stride schedule ----
    int bufn = 0;
    for (int item = blockIdx.x; item < NITEMS; item += PBLKS, bufn ^= 1) {
        __syncthreads();   // sp[bufn] staged & visible; prev readers of sp[bufn^1] done

        // Prefetch next item's scene chunk into the alternate buffer
        int nxt = item + PBLKS;
        if (nxt < NITEMS && tid < PITEM) {
            int bbn = nxt >> 9;
            int p0n = (nxt & 63) << 6;
            const float* spp = scene + ((size_t)bbn * NP + p0n + tid) * 3;
            sm.sp[bufn ^ 1][tid] = make_float4(spp[0], spp[1], spp[2], 0.f);
        }

        // Decode item
        const int bb = item >> 9;
        const int rem = item & 511;
        const int g = ((rem >> 6) << 3) + wid;
        const int p0 = (rem & 63) << 6;
        const float4* spb = sm.sp[bufn];

        // Pose -> rotation (per item, per warp)
        const float* pp = poses + ((size_t)(bb * NG + g)) * 7;
        float tx = pp[0], ty = pp[1], tz = pp[2];
        float qx = pp[3], qy = pp[4], qz = pp[5], qw = pp[6];
        float inv = 1.f / (sqrtf(qx * qx + qy * qy + qz * qz + qw * qw) + 1e-8f);
        qx *= inv; qy *= inv; qz *= inv; qw *= inv;
        float xx = qx * qx, yy = qy * qy, zz = qz * qz;
        float xy = qx * qy, xz = qx * qz, yz = qy * qz;
        float wx = qw * qx, wy = qw * qy, wz = qw * qz;
        float R00 = 1.f - 2.f * (yy + zz), R01 = 2.f * (xy - wz), R02 = 2.f * (xz + wy);
        float R10 = 2.f * (xy + wz), R11 = 1.f - 2.f * (xx + zz), R12 = 2.f * (yz - wx);
        float R20 = 2.f * (xz - wy), R21 = 2.f * (yz + wx), R22 = 1.f - 2.f * (xx + yy);

        const size_t outbase = (((size_t)bb * NH) * NG + g) * NP + p0;

        #pragma unroll
        for (int itp = 0; itp < 2; ++itp) {   // dual-tile passes: tiles 2itp, 2itp+1
            // ---- Geometry + A-frags for both tiles ----
            unsigned afx0[4], afx1[4];
            #pragma unroll
            for (int u = 0; u < 2; ++u) {
                int base = (2 * itp + u) * TILE;
                float4 PA = spb[base + gg];
                float4 PB = spb[base + gg + 8];
                float rxA = PA.x - tx, ryA = PA.y - ty, rzA = PA.z - tz;
                float lxA = R00 * rxA + R10 * ryA + R20 * rzA;
                float lyA = R01 * rxA + R11 * ryA + R21 * rzA;
                float lzA = R02 * rxA + R12 * ryA + R22 * rzA;
                float ddA = sqrtf(lxA * lxA + lyA * lyA + lzA * lzA);
                float rxB = PB.x - tx, ryB = PB.y - ty, rzB = PB.z - tz;
                float lxB = R00 * rxB + R10 * ryB + R20 * rzB;
                float lyB = R01 * rxB + R11 * ryB + R21 * rzB;
                float lzB = R02 * rxB + R12 * ryB + R22 * rzB;
                float ddB = sqrtf(lxB * lxB + lyB * lyB + lzB * lzB);
                float s0A = (t == 0) ? lxA : (t == 1) ? lzA : (t == 2) ? 1.f : 0.f;
                float s1A = (t == 0) ? lyA : (t == 1) ? ddA : 0.f;
                float s0B = (t == 0) ? lxB : (t == 1) ? lzB : (t == 2) ? 1.f : 0.f;
                float s1B = (t == 0) ? lyB : (t == 1) ? ddB : 0.f;
                unsigned* afx = u ? afx1 : afx0;
                afx[0] = pack_h2(s0A, s1A);
                afx[1] = pack_h2(s0B, s1B);
                afx[2] = afx[0];
                afx[3] = afx[1];
            }

            // ---- Fused B+C over kb: one weight sweep feeds BOTH tiles ----
            float d0[8][4], d1[8][4];
            #pragma unroll
            for (int nb = 0; nb < 8; ++nb) {
                d0[nb][0] = d0[nb][1] = d0[nb][2] = d0[nb][3] = 0.f;
                d1[nb][0] = d1[nb][1] = d1[nb][2] = d1[nb][3] = 0.f;
            }
            float sA0 = 0.f, qA0 = 0.f, sB0 = 0.f, qB0 = 0.f;
            float sA1 = 0.f, qA1 = 0.f, sB1 = 0.f, qB1 = 0.f;

            #pragma unroll
            for (int kb = 0; kb < 8; ++kb) {
                uint4 wb = sm.W1p[kb][lane];
                float e0[4] = {0.f, 0.f, 0.f, 0.f};
                float f0[4] = {0.f, 0.f, 0.f, 0.f};
                float e1[4] = {0.f, 0.f, 0.f, 0.f};
                float f1[4] = {0.f, 0.f, 0.f, 0.f};
                mma_f16(e0, afx0, wb.x, wb.y);   // tile0, n-block 2kb
                mma_f16(f0, afx0, wb.z, wb.w);   // tile0, n-block 2kb+1
                mma_f16(e1, afx1, wb.x, wb.y);   // tile1
                mma_f16(f1, afx1, wb.z, wb.w);
                // relu + stats + pack (tile0)
                float v0 = fmaxf(e0[0], 0.f), v1 = fmaxf(e0[1], 0.f);
                float v2 = fmaxf(e0[2], 0.f), v3 = fmaxf(e0[3], 0.f);
                float v4 = fmaxf(f0[0], 0.f), v5 = fmaxf(f0[1], 0.f);
                float v6 = fmaxf(f0[2], 0.f), v7 = fmaxf(f0[3], 0.f);
                sA0 += (v0 + v1) + (v4 + v5);
                qA0 = fmaf(v0, v0, fmaf(v1, v1, fmaf(v4, v4, fmaf(v5, v5, qA0))));
                sB0 += (v2 + v3) + (v6 + v7);
                qB0 = fmaf(v2, v2, fmaf(v3, v3, fmaf(v6, v6, fmaf(v7, v7, qB0))));
                unsigned a0f[4];
                a0f[0] = pack_h2(v0, v1);
                a0f[1] = pack_h2(v2, v3);
                a0f[2] = pack_h2(v4, v5);
                a0f[3] = pack_h2(v6, v7);
                // relu + stats + pack (tile1)
                float u0 = fmaxf(e1[0], 0.f), u1 = fmaxf(e1[1], 0.f);
                float u2 = fmaxf(e1[2], 0.f), u3 = fmaxf(e1[3], 0.f);
                float u4 = fmaxf(f1[0], 0.f), u5 = fmaxf(f1[1], 0.f);
                float u6 = fmaxf(f1[2], 0.f), u7 = fmaxf(f1[3], 0.f);
                sA1 += (u0 + u1) + (u4 + u5);
                qA1 = fmaf(u0, u0, fmaf(u1, u1, fmaf(u4, u4, fmaf(u5, u5, qA1))));
                sB1 += (u2 + u3) + (u6 + u7);
                qB1 = fmaf(u2, u2, fmaf(u3, u3, fmaf(u6, u6, fmaf(u7, u7, qB1))));
                unsigned a1f[4];
                a1f[0] = pack_h2(u0, u1);
                a1f[1] = pack_h2(u2, u3);
                a1f[2] = pack_h2(u4, u5);
                a1f[3] = pack_h2(u6, u7);
                // stage C: one Bp load serves both tiles
                #pragma unroll
                for (int nbp = 0; nbp < 4; ++nbp) {
                    uint4 bp = sm.Bp[kb][nbp][lane];
                    mma_f16(d0[2 * nbp],     a0f, bp.x, bp.y);
                    mma_f16(d0[2 * nbp + 1], a0f, bp.z, bp.w);
                    mma_f16(d1[2 * nbp],     a1f, bp.x, bp.y);
                    mma_f16(d1[2 * nbp + 1], a1f, bp.z, bp.w);
                }
            }

            // ---- LN1 stats reduce (both tiles together) ----
            #pragma unroll
            for (int o = 1; o <= 2; o <<= 1) {
                sA0 += __shfl_xor_sync(0xffffffffu, sA0, o);
                qA0 += __shfl_xor_sync(0xffffffffu, qA0, o);
                sB0 += __shfl_xor_sync(0xffffffffu, sB0, o);
                qB0 += __shfl_xor_sync(0xffffffffu, qB0, o);
                sA1 += __shfl_xor_sync(0xffffffffu, sA1, o);
                qA1 += __shfl_xor_sync(0xffffffffu, qA1, o);
                sB1 += __shfl_xor_sync(0xffffffffu, sB1, o);
                qB1 += __shfl_xor_sync(0xffffffffu, qB1, o);
            }
            float mu1A0 = sA0 * (1.f / 128.f);
            float rs1A0 = rsqrtf(fmaxf(qA0 * (1.f / 128.f) - mu1A0 * mu1A0, 0.f) + 1e-5f);
            float ng1A0 = -mu1A0 * rs1A0;
            float mu1B0 = sB0 * (1.f / 128.f);
            float rs1B0 = rsqrtf(fmaxf(qB0 * (1.f / 128.f) - mu1B0 * mu1B0, 0.f) + 1e-5f);
            float ng1B0 = -mu1B0 * rs1B0;
            float mu1A1 = sA1 * (1.f / 128.f);
            float rs1A1 = rsqrtf(fmaxf(qA1 * (1.f / 128.f) - mu1A1 * mu1A1, 0.f) + 1e-5f);
            float ng1A1 = -mu1A1 * rs1A1;
            float mu1B1 = sB1 * (1.f / 128.f);
            float rs1B1 = rsqrtf(fmaxf(qB1 * (1.f / 128.f) - mu1B1 * mu1B1, 0.f) + 1e-5f);
            float ng1B1 = -mu1B1 * rs1B1;

            // ---- MERGED epilogue + stage D: 4 independent mma chains ----
            float dh0[4] = {0.f, 0.f, 0.f, 0.f};
            float dl0[4] = {0.f, 0.f, 0.f, 0.f};
            float dh1[4] = {0.f, 0.f, 0.f, 0.f};
            float dl1[4] = {0.f, 0.f, 0.f, 0.f};
            float sg0 = 0.f, qg0 = 0.f, sh0 = 0.f, qh0 = 0.f;
            float sg1 = 0.f, qg1 = 0.f, sh1 = 0.f, qh1 = 0.f;
            #pragma unroll
            for (int kb2 = 0; kb2 < 4; ++kb2) {
                const int nb0 = 2 * kb2, nb1 = 2 * kb2 + 1;
                uint2 ge0 = sm.GEp[nb0][t];
                uint2 ge1 = sm.GEp[nb1][t];
                float2 G0 = unpack_h2(ge0.x), E0 = unpack_h2(ge0.y);
                float2 G1 = unpack_h2(ge1.x), E1 = unpack_h2(ge1.y);
                uint4 bd = sm.bDp[kb2][lane];
                // tile0 v's
                float v00 = fmaxf(fmaf(rs1A0, d0[nb0][0], fmaf(ng1A0, G0.x, E0.x)), 0.f);
                float v01 = fmaxf(fmaf(rs1A0, d0[nb0][1], fmaf(ng1A0, G0.y, E0.y)), 0.f);
                float v10 = fmaxf(fmaf(rs1B0, d0[nb0][2], fmaf(ng1B0, G0.x, E0.x)), 0.f);
                float v11 = fmaxf(fmaf(rs1B0, d0[nb0][3], fmaf(ng1B0, G0.y, E0.y)), 0.f);
                float v20 = fmaxf(fmaf(rs1A0, d0[nb1][0], fmaf(ng1A0, G1.x, E1.x)), 0.f);
                float v21 = fmaxf(fmaf(rs1A0, d0[nb1][1], fmaf(ng1A0, G1.y, E1.y)), 0.f);
                float v30 = fmaxf(fmaf(rs1B0, d0[nb1][2], fmaf(ng1B0, G1.x, E1.x)), 0.f);
                float v31 = fmaxf(fmaf(rs1B0, d0[nb1][3], fmaf(ng1B0, G1.y, E1.y)), 0.f);
                sg0 += (v00 + v01) + (v20 + v21);
                qg0 = fmaf(v00, v00, fmaf(v01, v01, fmaf(v20, v20, fmaf(v21, v21, qg0))));
                sh0 += (v10 + v11) + (v30 + v31);
                qh0 = fmaf(v10, v10, fmaf(v11, v11, fmaf(v30, v30, fmaf(v31, v31, qh0))));
                unsigned av0[4];
                av0[0] = pack_h2(v00, v01);
                av0[1] = pack_h2(v10, v11);
                av0[2] = pack_h2(v20, v21);
                av0[3] = pack_h2(v30, v31);
                // tile1 v's
                float w00 = fmaxf(fmaf(rs1A1, d1[nb0][0], fmaf(ng1A1, G0.x, E0.x)), 0.f);
                float w01 = fmaxf(fmaf(rs1A1, d1[nb0][1], fmaf(ng1A1, G0.y, E0.y)), 0.f);
                float w10 = fmaxf(fmaf(rs1B1, d1[nb0][2], fmaf(ng1B1, G0.x, E0.x)), 0.f);
                float w11 = fmaxf(fmaf(rs1B1, d1[nb0][3], fmaf(ng1B1, G0.y, E0.y)), 0.f);
                float w20 = fmaxf(fmaf(rs1A1, d1[nb1][0], fmaf(ng1A1, G1.x, E1.x)), 0.f);
                float w21 = fmaxf(fmaf(rs1A1, d1[nb1][1], fmaf(ng1A1, G1.y, E1.y)), 0.f);
                float w30 = fmaxf(fmaf(rs1B1, d1[nb1][2], fmaf(ng1B1, G1.x, E1.x)), 0.f);
                float w31 = fmaxf(fmaf(rs1B1, d1[nb1][3], fmaf(ng1B1, G1.y, E1.y)), 0.f);
                sg1 += (w00 + w01) + (w20 + w21);
                qg1 = fmaf(w00, w00, fmaf(w01, w01, fmaf(w20, w20, fmaf(w21, w21, qg1))));
                sh1 += (w10 + w11) + (w30 + w31);
                qh1 = fmaf(w10, w10, fmaf(w11, w11, fmaf(w30, w30, fmaf(w31, w31, qh1))));
                unsigned av1[4];
                av1[0] = pack_h2(w00, w01);
                av1[1] = pack_h2(w10, w11);
                av1[2] = pack_h2(w20, w21);
                av1[3] = pack_h2(w30, w31);
                // 4 independent chains
                mma_f16(dh0, av0, bd.x, bd.y);
                mma_f16(dh1, av1, bd.x, bd.y);
                mma_f16(dl0, av0, bd.z, bd.w);
                mma_f16(dl1, av1, bd.z, bd.w);
            }
            // merged LN2 stats reduce (both tiles)
            #pragma unroll
            for (int o = 1; o <= 2; o <<= 1) {
                sg0 += __shfl_xor_sync(0xffffffffu, sg0, o);
                qg0 += __shfl_xor_sync(0xffffffffu, qg0, o);
                sh0 += __shfl_xor_sync(0xffffffffu, sh0, o);
                qh0 += __shfl_xor_sync(0xffffffffu, qh0, o);
                sg1 += __shfl_xor_sync(0xffffffffu, sg1, o);
                qg1 += __shfl_xor_sync(0xffffffffu, qg1, o);
                sh1 += __shfl_xor_sync(0xffffffffu, sh1, o);
                qh1 += __shfl_xor_sync(0xffffffffu, qh1, o);
            }

            // ---- Outputs, tile0 then tile1 ----
            #pragma unroll
            for (int u = 0; u < 2; ++u) {
                float sg = u ? sg1 : sg0, qg = u ? qg1 : qg0;
                float sh = u ? sh1 : sh0, qh = u ? qh1 : qh0;
                const float* dh = u ? dh1 : dh0;
                const float* dl = u ? dl1 : dl0;
                float muA = sg * (1.f / 64.f);
                float rsA = rsqrtf(fmaxf(qg * (1.f / 64.f) - muA * muA, 0.f) + 1e-5f);
                float muB = sh * (1.f / 64.f);
                float rsB = rsqrtf(fmaxf(qh * (1.f / 64.f) - muB * muB, 0.f) + 1e-5f);

                const int pw = (2 * itp + u) * TILE;
                float* oA = out + outbase + (size_t)(2 * t) * (NG * NP) + pw;
                float* oB = out + outbase + (size_t)(2 * t + 1) * (NG * NP) + pw;
                float m1 = rsA * bsa, m2 = rsA * bsb;
                float m3 = rsB * bsa, m4 = rsB * bsb;
                oA[gg]     = fmaf(dh[0] + dl[0], m1, fmaf(-muA * m1, K2a, C0a));
                oB[gg]     = fmaf(dh[1] + dl[1], m2, fmaf(-muA * m2, K2b, C0b));
                oA[gg + 8] = fmaf(dh[2] + dl[2], m3, fmaf(-muB * m3, K2a, C0a));
                oB[gg + 8] = fmaf(dh[3] + dl[3], m4, fmaf(-muB * m4, K2b, C0b));
            }
        }
    }
}

extern "C" void kernel_launch(void* const* d_in, const int* in_sizes, int n_in,
                              void* d_out, int out_size) {
    // metadata order: grasp_tokens, scene_points, grasp_poses, W1, b1, g1, beta1,
    //                 W2, b2, g2, beta2, W3, b3, bias_scale
    const float* scene  = (const float*)d_in[1];
    const float* poses  = (const float*)d_in[2];
    const float* W1     = (const float*)d_in[3];
    const float* b1     = (const float*)d_in[4];
    const float* g1     = (const float*)d_in[5];
    const float* be1    = (const float*)d_in[6];
    const float* W2     = (const float*)d_in[7];
    const float* b2     = (const float*)d_in[8];
    const float* g2     = (const float*)d_in[9];
    const float* be2    = (const float*)d_in[10];
    const float* W3     = (const float*)d_in[11];
    const float* b3     = (const float*)d_in[12];
    const float* bscale = (const float*)d_in[13];
    float* out = (float*)d_out;

    cudaFuncSetAttribute(gab_kernel, cudaFuncAttributeMaxDynamicSharedMemorySize,
                         (int)sizeof(Smem));
    gab_kernel<<<PBLKS, 256, sizeof(Smem)>>>(scene, poses, W1, b1, g1, be1,
                                             W2, b2, g2, be2, W3, b3, bscale, out);
}

// round 16
// speedup vs baseline: 1.0284x; 1.0284x over previous
#include <cuda_runtime.h>
#include <cuda_fp16.h>
#include <cstdint>

// Problem dims (fixed by setup_inputs)
#define BATCH 4
#define NG 64
#define NH 8
#define NP 4096
#define TILE 16
#define PITEM 64              // points per work item (4 tiles = 2 dual-tile passes)
#define NITEMS 2048           // 4 b * 8 gchunks * 64 pchunks
#define PBLKS 296             // 148 SMs * 2 blocks -> one full wave

struct __align__(16) Smem {
    uint4  Bp[8][4][32];      // W2' frags, nb-paired                      16 KB
    uint4  W1p[8][32];        // W1' frags {h0,l0,h1,l1}                    4 KB
    float4 sp[2][PITEM];      // scene points, double-buffered              2 KB
    uint2  bDp[4][32];        // stage-D A3 frags {h0,h1} (single-term)     1 KB
    float4 GEp[8][4];         // {G0,G1,E0,E1} fp32 per (nb, t)            512 B
};                             // ~23.5 KB total

// fp16 split: hi + residual lo, packed fp16x2 (x0 low).
__device__ __forceinline__ void split2h(float x0, float x1, unsigned& hi, unsigned& lo) {
    asm("cvt.rn.f16x2.f32 %0, %1, %2;" : "=r"(hi) : "f"(x1), "f"(x0));
    __half2 hv = *reinterpret_cast<__half2*>(&hi);
    float2 back = __half22float2(hv);
    asm("cvt.rn.f16x2.f32 %0, %1, %2;" : "=r"(lo) : "f"(x1 - back.y), "f"(x0 - back.x));
}
__device__ __forceinline__ unsigned pack_h2(float x0, float x1) {
    unsigned u;
    asm("cvt.rn.f16x2.f32 %0, %1, %2;" : "=r"(u) : "f"(x1), "f"(x0));
    return u;
}
__device__ __forceinline__ void mma_f16(float d[4], const unsigned a[4],
                                        unsigned b0, unsigned b1) {
    asm volatile(
        "mma.sync.aligned.m16n8k16.row.col.f32.f16.f16.f32 "
        "{%0,%1,%2,%3},{%4,%5,%6,%7},{%8,%9},{%0,%1,%2,%3};"
        : "+f"(d[0]), "+f"(d[1]), "+f"(d[2]), "+f"(d[3])
        : "r"(a[0]), "r"(a[1]), "r"(a[2]), "r"(a[3]), "r"(b0), "r"(b1));
}

__global__ void __launch_bounds__(256, 2)
gab_kernel(const float* __restrict__ scene,   // (B, NP, 3)
           const float* __restrict__ poses,   // (B, NG, 7)
           const float* __restrict__ W1, const float* __restrict__ b1,
           const float* __restrict__ g1, const float* __restrict__ be1,
           const float* __restrict__ W2, const float* __restrict__ b2,
           const float* __restrict__ g2, const float* __restrict__ be2,
           const float* __restrict__ W3, const float* __restrict__ b3,
           const float* __restrict__ bscale,
           float* __restrict__ out)            // (B, NH, NG, NP)
{
    extern __shared__ __align__(16) char smraw[];
    Smem& sm = *reinterpret_cast<Smem*>(smraw);

    const int tid = threadIdx.x;

    // ---- Once-per-block prologue (all g-independent) ----
    for (int idx = tid; idx < 8 * 4 * 32; idx += 256) {
        int kb = idx >> 7, rem = idx & 127;
        int nbp = rem >> 5, ln = rem & 31;
        int tt = ln & 3, c = ln >> 2;
        int n0 = (2 * nbp) * 8 + c, n1 = (2 * nbp + 1) * 8 + c;
        int k0 = kb * 16 + 2 * tt;
        float g0 = g1[k0 + 0], g1v = g1[k0 + 1], g8 = g1[k0 + 8], g9 = g1[k0 + 9];
        unsigned x = pack_h2(g0 * W2[(k0 + 0) * 64 + n0], g1v * W2[(k0 + 1) * 64 + n0]);
        unsigned y = pack_h2(g8 * W2[(k0 + 8) * 64 + n0], g9 * W2[(k0 + 9) * 64 + n0]);
        unsigned z = pack_h2(g0 * W2[(k0 + 0) * 64 + n1], g1v * W2[(k0 + 1) * 64 + n1]);
        unsigned w = pack_h2(g8 * W2[(k0 + 8) * 64 + n1], g9 * W2[(k0 + 9) * 64 + n1]);
        sm.Bp[kb][nbp][ln] = make_uint4(x, y, z, w);
    }
    for (int idx = tid; idx < 8 * 32; idx += 256) {
        int kbp = idx >> 5, ln = idx & 31;
        int tt = ln & 3, c = ln >> 2;
        int k0 = 2 * tt, k1 = 2 * tt + 1;
        int n0 = (2 * kbp) * 8 + c, n1 = (2 * kbp + 1) * 8 + c;
        // W1' rows: 0-3 = W1, 4 = b1, 5-7 = 0
        float w00 = (k0 < 4) ? W1[k0 * 128 + n0] : (k0 == 4 ? b1[n0] : 0.f);
        float w01 = (k1 < 4) ? W1[k1 * 128 + n0] : (k1 == 4 ? b1[n0] : 0.f);
        float w10 = (k0 < 4) ? W1[k0 * 128 + n1] : (k0 == 4 ? b1[n1] : 0.f);
        float w11 = (k1 < 4) ? W1[k1 * 128 + n1] : (k1 == 4 ? b1[n1] : 0.f);
        unsigned h0, l0, h1, l1;
        split2h(w00, w01, h0, l0);
        split2h(w10, w11, h1, l1);
        sm.W1p[kbp][ln] = make_uint4(h0, l0, h1, l1);
    }
    if (tid < 128) {      // stage-D A3 fragments (single fp16 term)
        int kb2 = tid >> 5, ln = tid & 31;
        int tt = ln & 3, gg2 = ln >> 2;
        int k0 = kb2 * 16 + 2 * tt;
        float a0 = g2[k0 + 0] * W3[(k0 + 0) * 8 + gg2];
        float a1 = g2[k0 + 1] * W3[(k0 + 1) * 8 + gg2];
        float a2 = g2[k0 + 8] * W3[(k0 + 8) * 8 + gg2];
        float a3 = g2[k0 + 9] * W3[(k0 + 9) * 8 + gg2];
        sm.bDp[kb2][ln] = make_uint2(pack_h2(a0, a1), pack_h2(a2, a3));
    }
    if (tid >= 128 && tid < 160) {   // G/EB fold vectors, fp32
        int j = tid - 128;
        int nb = j >> 2, tt = j & 3;
        int n0 = nb * 8 + 2 * tt, n1 = n0 + 1;
        float G0 = 0.f, G1 = 0.f, E0 = 0.f, E1 = 0.f;
        #pragma unroll 4
        for (int k = 0; k < 128; ++k) {
            float gk = g1[k], bk = be1[k];
            float w0 = W2[k * 64 + n0], w1 = W2[k * 64 + n1];
            G0 = fmaf(gk, w0, G0); G1 = fmaf(gk, w1, G1);
            E0 = fmaf(bk, w0, E0); E1 = fmaf(bk, w1, E1);
        }
        sm.GEp[nb][tt] = make_float4(G0, G1, E0 + b2[n0], E1 + b2[n1]);
    }
    // Stage first item's scene chunk into buffer 0
    {
        int item0 = blockIdx.x;
        if (item0 < NITEMS && tid < PITEM) {
            int bb = item0 >> 9;
            int p0 = (item0 & 63) << 6;
            const float* spp = scene + ((size_t)bb * NP + p0 + tid) * 3;
            sm.sp[0][tid] = make_float4(spp[0], spp[1], spp[2], 0.f);
        }
    }
    __syncthreads();

    const int wid = tid >> 5, lane = tid & 31;
    const int t = lane & 3, gg = lane >> 2;   // mma fragment coords

    // ---- Per-head fold constants for heads h0 = 2t, h1 = 2t+1 (g-independent) ----
    float K2a = 0.f, K2b = 0.f, K1a = 0.f, K1b = 0.f;
    #pragma unroll 8
    for (int c = 0; c < 64; ++c) {
        float2 w = *reinterpret_cast<const float2*>(W3 + c * 8 + 2 * t);
        float gc = __ldg(g2 + c), bc = __ldg(be2 + c);
        K2a = fmaf(gc, w.x, K2a); K2b = fmaf(gc, w.y, K2b);
        K1a = fmaf(bc, w.x, K1a); K1b = fmaf(bc, w.y, K1b);
    }
    const float bsa = __ldg(bscale + 2 * t), bsb = __ldg(bscale + 2 * t + 1);
    const float C0a = (K1a + __ldg(b3 + 2 * t)) * bsa;
    const float C0b = (K1b + __ldg(b3 + 2 * t + 1)) * bsb;

    // ---- Persistent item loop: static stride schedule ----
    int bufn = 0;
    for (int item = blockIdx.x; item < NITEMS; item += PBLKS, bufn ^= 1) {
        __syncthreads();   // sp[bufn] staged & visible; prev readers of sp[bufn^1] done

        // Prefetch next item's scene chunk into the alternate buffer
        int nxt = item + PBLKS;
        if (nxt < NITEMS && tid < PITEM) {
            int bbn = nxt >> 9;
            int p0n = (nxt & 63) << 6;
            const float* spp = scene + ((size_t)bbn * NP + p0n + tid) * 3;
            sm.sp[bufn ^ 1][tid] = make_float4(spp[0], spp[1], spp[2], 0.f);
        }

        // Decode item
        const int bb = item >> 9;
        const int rem = item & 511;
        const int g = ((rem >> 6) << 3) + wid;
        const int p0 = (rem & 63) << 6;
        const float4* spb = sm.sp[bufn];

        // Pose -> rotation (per item, per warp)
        const float* pp = poses + ((size_t)(bb * NG + g)) * 7;
        float tx = pp[0], ty = pp[1], tz = pp[2];
        float qx = pp[3], qy = pp[4], qz = pp[5], qw = pp[6];
        float inv = 1.f / (sqrtf(qx * qx + qy * qy + qz * qz + qw * qw) + 1e-8f);
        qx *= inv; qy *= inv; qz *= inv; qw *= inv;
        float xx = qx * qx, yy = qy * qy, zz = qz * qz;
        float xy = qx * qy, xz = qx * qz, yz = qy * qz;
        float wx = qw * qx, wy = qw * qy, wz = qw * qz;
        float R00 = 1.f - 2.f * (yy + zz), R01 = 2.f * (xy - wz), R02 = 2.f * (xz + wy);
        float R10 = 2.f * (xy + wz), R11 = 1.f - 2.f * (xx + zz), R12 = 2.f * (yz - wx);
        float R20 = 2.f * (xz - wy), R21 = 2.f * (yz + wx), R22 = 1.f - 2.f * (xx + yy);

        const size_t outbase = (((size_t)bb * NH) * NG + g) * NP + p0;

        #pragma unroll
        for (int itp = 0; itp < 2; ++itp) {   // dual-tile passes: tiles 2itp, 2itp+1
            // ---- Geometry + A-frags for both tiles ----
            unsigned afx0[4], afx1[4];
            #pragma unroll
            for (int u = 0; u < 2; ++u) {
                int base = (2 * itp + u) * TILE;
                float4 PA = spb[base + gg];
                float4 PB = spb[base + gg + 8];
                float rxA = PA.x - tx, ryA = PA.y - ty, rzA = PA.z - tz;
                float lxA = R00 * rxA + R10 * ryA + R20 * rzA;
                float lyA = R01 * rxA + R11 * ryA + R21 * rzA;
                float lzA = R02 * rxA + R12 * ryA + R22 * rzA;
                float ddA = sqrtf(lxA * lxA + lyA * lyA + lzA * lzA);
                float rxB = PB.x - tx, ryB = PB.y - ty, rzB = PB.z - tz;
                float lxB = R00 * rxB + R10 * ryB + R20 * rzB;
                float lyB = R01 * rxB + R11 * ryB + R21 * rzB;
                float lzB = R02 * rxB + R12 * ryB + R22 * rzB;
                float ddB = sqrtf(lxB * lxB + lyB * lyB + lzB * lzB);
                float s0A = (t == 0) ? lxA : (t == 1) ? lzA : (t == 2) ? 1.f : 0.f;
                float s1A = (t == 0) ? lyA : (t == 1) ? ddA : 0.f;
                float s0B = (t == 0) ? lxB : (t == 1) ? lzB : (t == 2) ? 1.f : 0.f;
                float s1B = (t == 0) ? lyB : (t == 1) ? ddB : 0.f;
                unsigned* afx = u ? afx1 : afx0;
                afx[0] = pack_h2(s0A, s1A);
                afx[1] = pack_h2(s0B, s1B);
                afx[2] = afx[0];
                afx[3] = afx[1];
            }

            // ---- Fused B+C over kb: one weight sweep feeds BOTH tiles ----
            float d0[8][4], d1[8][4];
            #pragma unroll
            for (int nb = 0; nb < 8; ++nb) {
                d0[nb][0] = d0[nb][1] = d0[nb][2] = d0[nb][3] = 0.f;
                d1[nb][0] = d1[nb][1] = d1[nb][2] = d1[nb][3] = 0.f;
            }
            float sA0 = 0.f, qA0 = 0.f, sB0 = 0.f, qB0 = 0.f;
            float sA1 = 0.f, qA1 = 0.f, sB1 = 0.f, qB1 = 0.f;

            #pragma unroll
            for (int kb = 0; kb < 8; ++kb) {
                uint4 wb = sm.W1p[kb][lane];
                float e0[4] = {0.f, 0.f, 0.f, 0.f};
                float f0[4] = {0.f, 0.f, 0.f, 0.f};
                float e1[4] = {0.f, 0.f, 0.f, 0.f};
                float f1[4] = {0.f, 0.f, 0.f, 0.f};
                mma_f16(e0, afx0, wb.x, wb.y);   // tile0, n-block 2kb
                mma_f16(f0, afx0, wb.z, wb.w);   // tile0, n-block 2kb+1
                mma_f16(e1, afx1, wb.x, wb.y);   // tile1
                mma_f16(f1, afx1, wb.z, wb.w);
                // relu + stats + pack (tile0)
                float v0 = fmaxf(e0[0], 0.f), v1 = fmaxf(e0[1], 0.f);
                float v2 = fmaxf(e0[2], 0.f), v3 = fmaxf(e0[3], 0.f);
                float v4 = fmaxf(f0[0], 0.f), v5 = fmaxf(f0[1], 0.f);
                float v6 = fmaxf(f0[2], 0.f), v7 = fmaxf(f0[3], 0.f);
                sA0 += (v0 + v1) + (v4 + v5);
                qA0 = fmaf(v0, v0, fmaf(v1, v1, fmaf(v4, v4, fmaf(v5, v5, qA0))));
                sB0 += (v2 + v3) + (v6 + v7);
                qB0 = fmaf(v2, v2, fmaf(v3, v3, fmaf(v6, v6, fmaf(v7, v7, qB0))));
                unsigned a0f[4];
                a0f[0] = pack_h2(v0, v1);
                a0f[1] = pack_h2(v2, v3);
                a0f[2] = pack_h2(v4, v5);
                a0f[3] = pack_h2(v6, v7);
                // relu + stats + pack (tile1)
                float u0 = fmaxf(e1[0], 0.f), u1 = fmaxf(e1[1], 0.f);
                float u2 = fmaxf(e1[2], 0.f), u3 = fmaxf(e1[3], 0.f);
                float u4 = fmaxf(f1[0], 0.f), u5 = fmaxf(f1[1], 0.f);
                float u6 = fmaxf(f1[2], 0.f), u7 = fmaxf(f1[3], 0.f);
                sA1 += (u0 + u1) + (u4 + u5);
                qA1 = fmaf(u0, u0, fmaf(u1, u1, fmaf(u4, u4, fmaf(u5, u5, qA1))));
                sB1 += (u2 + u3) + (u6 + u7);
                qB1 = fmaf(u2, u2, fmaf(u3, u3, fmaf(u6, u6, fmaf(u7, u7, qB1))));
                unsigned a1f[4];
                a1f[0] = pack_h2(u0, u1);
                a1f[1] = pack_h2(u2, u3);
                a1f[2] = pack_h2(u4, u5);
                a1f[3] = pack_h2(u6, u7);
                // stage C: one Bp load serves both tiles
                #pragma unroll
                for (int nbp = 0; nbp < 4; ++nbp) {
                    uint4 bp = sm.Bp[kb][nbp][lane];
                    mma_f16(d0[2 * nbp],     a0f, bp.x, bp.y);
                    mma_f16(d0[2 * nbp + 1], a0f, bp.z, bp.w);
                    mma_f16(d1[2 * nbp],     a1f, bp.x, bp.y);
                    mma_f16(d1[2 * nbp + 1], a1f, bp.z, bp.w);
                }
            }

            // ---- LN1 stats reduce (both tiles together) ----
            #pragma unroll
            for (int o = 1; o <= 2; o <<= 1) {
                sA0 += __shfl_xor_sync(0xffffffffu, sA0, o);
                qA0 += __shfl_xor_sync(0xffffffffu, qA0, o);
                sB0 += __shfl_xor_sync(0xffffffffu, sB0, o);
                qB0 += __shfl_xor_sync(0xffffffffu, qB0, o);
                sA1 += __shfl_xor_sync(0xffffffffu, sA1, o);
                qA1 += __shfl_xor_sync(0xffffffffu, qA1, o);
                sB1 += __shfl_xor_sync(0xffffffffu, sB1, o);
                qB1 += __shfl_xor_sync(0xffffffffu, qB1, o);
            }
            float mu1A0 = sA0 * (1.f / 128.f);
            float rs1A0 = rsqrtf(fmaxf(qA0 * (1.f / 128.f) - mu1A0 * mu1A0, 0.f) + 1e-5f);
            float ng1A0 = -mu1A0 * rs1A0;
            float mu1B0 = sB0 * (1.f / 128.f);
            float rs1B0 = rsqrtf(fmaxf(qB0 * (1.f / 128.f) - mu1B0 * mu1B0, 0.f) + 1e-5f);
            float ng1B0 = -mu1B0 * rs1B0;
            float mu1A1 = sA1 * (1.f / 128.f);
            float rs1A1 = rsqrtf(fmaxf(qA1 * (1.f / 128.f) - mu1A1 * mu1A1, 0.f) + 1e-5f);
            float ng1A1 = -mu1A1 * rs1A1;
            float mu1B1 = sB1 * (1.f / 128.f);
            float rs1B1 = rsqrtf(fmaxf(qB1 * (1.f / 128.f) - mu1B1 * mu1B1, 0.f) + 1e-5f);
            float ng1B1 = -mu1B1 * rs1B1;

            // ---- MERGED epilogue + stage D (single-term A3, fp32 G/EB) ----
            float dh0[4] = {0.f, 0.f, 0.f, 0.f};
            float dh1[4] = {0.f, 0.f, 0.f, 0.f};
            float sg0 = 0.f, qg0 = 0.f, sh0 = 0.f, qh0 = 0.f;
            float sg1 = 0.f, qg1 = 0.f, sh1 = 0.f, qh1 = 0.f;
            #pragma unroll
            for (int kb2 = 0; kb2 < 4; ++kb2) {
                const int nb0 = 2 * kb2, nb1 = 2 * kb2 + 1;
                float4 ge0 = sm.GEp[nb0][t];   // {G0x, G0y, E0x, E0y}
                float4 ge1 = sm.GEp[nb1][t];
                uint2 bd = sm.bDp[kb2][lane];
                // tile0 v's
                float v00 = fmaxf(fmaf(rs1A0, d0[nb0][0], fmaf(ng1A0, ge0.x, ge0.z)), 0.f);
                float v01 = fmaxf(fmaf(rs1A0, d0[nb0][1], fmaf(ng1A0, ge0.y, ge0.w)), 0.f);
                float v10 = fmaxf(fmaf(rs1B0, d0[nb0][2], fmaf(ng1B0, ge0.x, ge0.z)), 0.f);
                float v11 = fmaxf(fmaf(rs1B0, d0[nb0][3], fmaf(ng1B0, ge0.y, ge0.w)), 0.f);
                float v20 = fmaxf(fmaf(rs1A0, d0[nb1][0], fmaf(ng1A0, ge1.x, ge1.z)), 0.f);
                float v21 = fmaxf(fmaf(rs1A0, d0[nb1][1], fmaf(ng1A0, ge1.y, ge1.w)), 0.f);
                float v30 = fmaxf(fmaf(rs1B0, d0[nb1][2], fmaf(ng1B0, ge1.x, ge1.z)), 0.f);
                float v31 = fmaxf(fmaf(rs1B0, d0[nb1][3], fmaf(ng1B0, ge1.y, ge1.w)), 0.f);
                sg0 += (v00 + v01) + (v20 + v21);
                qg0 = fmaf(v00, v00, fmaf(v01, v01, fmaf(v20, v20, fmaf(v21, v21, qg0))));
                sh0 += (v10 + v11) + (v30 + v31);
                qh0 = fmaf(v10, v10, fmaf(v11, v11, fmaf(v30, v30, fmaf(v31, v31, qh0))));
                unsigned av0[4];
                av0[0] = pack_h2(v00, v01);
                av0[1] = pack_h2(v10, v11);
                av0[2] = pack_h2(v20, v21);
                av0[3] = pack_h2(v30, v31);
                // tile1 v's
                float w00 = fmaxf(fmaf(rs1A1, d1[nb0][0], fmaf(ng1A1, ge0.x, ge0.z)), 0.f);
                float w01 = fmaxf(fmaf(rs1A1, d1[nb0][1], fmaf(ng1A1, ge0.y, ge0.w)), 0.f);
                float w10 = fmaxf(fmaf(rs1B1, d1[nb0][2], fmaf(ng1B1, ge0.x, ge0.z)), 0.f);
                float w11 = fmaxf(fmaf(rs1B1, d1[nb0][3], fmaf(ng1B1, ge0.y, ge0.w)), 0.f);
                float w20 = fmaxf(fmaf(rs1A1, d1[nb1][0], fmaf(ng1A1, ge1.x, ge1.z)), 0.f);
                float w21 = fmaxf(fmaf(rs1A1, d1[nb1][1], fmaf(ng1A1, ge1.y, ge1.w)), 0.f);
                float w30 = fmaxf(fmaf(rs1B1, d1[nb1][2], fmaf(ng1B1, ge1.x, ge1.z)), 0.f);
                float w31 = fmaxf(fmaf(rs1B1, d1[nb1][3], fmaf(ng1B1, ge1.y, ge1.w)), 0.f);
                sg1 += (w00 + w01) + (w20 + w21);
                qg1 = fmaf(w00, w00, fmaf(w01, w01, fmaf(w20, w20, fmaf(w21, w21, qg1))));
                sh1 += (w10 + w11) + (w30 + w31);
                qh1 = fmaf(w10, w10, fmaf(w11, w11, fmaf(w30, w30, fmaf(w31, w31, qh1))));
                unsigned av1[4];
                av1[0] = pack_h2(w00, w01);
                av1[1] = pack_h2(w10, w11);
                av1[2] = pack_h2(w20, w21);
                av1[3] = pack_h2(w30, w31);
                // 2 independent chains (single-term A3)
                mma_f16(dh0, av0, bd.x, bd.y);
                mma_f16(dh1, av1, bd.x, bd.y);
            }
            // merged LN2 stats reduce (both tiles)
            #pragma unroll
            for (int o = 1; o <= 2; o <<= 1) {
                sg0 += __shfl_xor_sync(0xffffffffu, sg0, o);
                qg0 += __shfl_xor_sync(0xffffffffu, qg0, o);
                sh0 += __shfl_xor_sync(0xffffffffu, sh0, o);
                qh0 += __shfl_xor_sync(0xffffffffu, qh0, o);
                sg1 += __shfl_xor_sync(0xffffffffu, sg1, o);
                qg1 += __shfl_xor_sync(0xffffffffu, qg1, o);
                sh1 += __shfl_xor_sync(0xffffffffu, sh1, o);
                qh1 += __shfl_xor_sync(0xffffffffu, qh1, o);
            }

            // ---- Outputs, tile0 then tile1 ----
            #pragma unroll
            for (int u = 0; u < 2; ++u) {
                float sg = u ? sg1 : sg0, qg = u ? qg1 : qg0;
                float sh = u ? sh1 : sh0, qh = u ? qh1 : qh0;
                const float* dh = u ? dh1 : dh0;
                float muA = sg * (1.f / 64.f);
                float rsA = rsqrtf(fmaxf(qg * (1.f / 64.f) - muA * muA, 0.f) + 1e-5f);
                float muB = sh * (1.f / 64.f);
                float rsB = rsqrtf(fmaxf(qh * (1.f / 64.f) - muB * muB, 0.f) + 1e-5f);

                const int pw = (2 * itp + u) * TILE;
                float* oA = out + outbase + (size_t)(2 * t) * (NG * NP) + pw;
                float* oB = out + outbase + (size_t)(2 * t + 1) * (NG * NP) + pw;
                float m1 = rsA * bsa, m2 = rsA * bsb;
                float m3 = rsB * bsa, m4 = rsB * bsb;
                oA[gg]     = fmaf(dh[0], m1, fmaf(-muA * m1, K2a, C0a));
                oB[gg]     = fmaf(dh[1], m2, fmaf(-muA * m2, K2b, C0b));
                oA[gg + 8] = fmaf(dh[2], m3, fmaf(-muB * m3, K2a, C0a));
                oB[gg + 8] = fmaf(dh[3], m4, fmaf(-muB * m4, K2b, C0b));
            }
        }
    }
}

extern "C" void kernel_launch(void* const* d_in, const int* in_sizes, int n_in,
                              void* d_out, int out_size) {
    // metadata order: grasp_tokens, scene_points, grasp_poses, W1, b1, g1, beta1,
    //                 W2, b2, g2, beta2, W3, b3, bias_scale
    const float* scene  = (const float*)d_in[1];
    const float* poses  = (const float*)d_in[2];
    const float* W1     = (const float*)d_in[3];
    const float* b1     = (const float*)d_in[4];
    const float* g1     = (const float*)d_in[5];
    const float* be1    = (const float*)d_in[6];
    const float* W2     = (const float*)d_in[7];
    const float* b2     = (const float*)d_in[8];
    const float* g2     = (const float*)d_in[9];
    const float* be2    = (const float*)d_in[10];
    const float* W3     = (const float*)d_in[11];
    const float* b3     = (const float*)d_in[12];
    const float* bscale = (const float*)d_in[13];
    float* out = (float*)d_out;

    cudaFuncSetAttribute(gab_kernel, cudaFuncAttributeMaxDynamicSharedMemorySize,
                         (int)sizeof(Smem));
    gab_kernel<<<PBLKS, 256, sizeof(Smem)>>>(scene, poses, W1, b1, g1, be1,
                                             W2, b2, g2, be2, W3, b3, bscale, out);
}

// round 17
// speedup vs baseline: 1.0469x; 1.0179x over previous
#include <cuda_runtime.h>
#include <cuda_fp16.h>
#include <cstdint>

// Problem dims (fixed by setup_inputs)
#define BATCH 4
#define NG 64
#define NH 8
#define NP 4096
#define TILE 16
#define PITEM 64              // points per work item (4 tiles = 2 dual-tile passes)
#define NITEMS 2048           // 4 b * 8 gchunks * 64 pchunks
#define PBLKS 296             // 148 SMs * 2 blocks -> one full wave

struct __align__(16) Smem {
    uint4  Bp[8][4][32];      // W2' frags, nb-paired                      16 KB
    uint2  W1p[8][32];        // W1' k8 frags {nb even, nb odd}, single-term 2 KB
    float4 sp[2][PITEM];      // scene points, double-buffered              2 KB
    uint2  bDp[4][32];        // stage-D A3 frags {h0,h1} (single-term)     1 KB
    float4 GEp[8][4];         // {G0,G1,E0,E1} fp32 per (nb, t)            512 B
};                             // ~21.5 KB total

__device__ __forceinline__ unsigned pack_h2(float x0, float x1) {
    unsigned u;
    asm("cvt.rn.f16x2.f32 %0, %1, %2;" : "=r"(u) : "f"(x1), "f"(x0));
    return u;
}
__device__ __forceinline__ void mma_f16(float d[4], const unsigned a[4],
                                        unsigned b0, unsigned b1) {
    asm volatile(
        "mma.sync.aligned.m16n8k16.row.col.f32.f16.f16.f32 "
        "{%0,%1,%2,%3},{%4,%5,%6,%7},{%8,%9},{%0,%1,%2,%3};"
        : "+f"(d[0]), "+f"(d[1]), "+f"(d[2]), "+f"(d[3])
        : "r"(a[0]), "r"(a[1]), "r"(a[2]), "r"(a[3]), "r"(b0), "r"(b1));
}
__device__ __forceinline__ void mma_f16_k8(float d[4], unsigned a0, unsigned a1,
                                           unsigned b0) {
    asm volatile(
        "mma.sync.aligned.m16n8k8.row.col.f32.f16.f16.f32 "
        "{%0,%1,%2,%3},{%4,%5},{%6},{%0,%1,%2,%3};"
        : "+f"(d[0]), "+f"(d[1]), "+f"(d[2]), "+f"(d[3])
        : "r"(a0), "r"(a1), "r"(b0));
}

__global__ void __launch_bounds__(256, 2)
gab_kernel(const float* __restrict__ scene,   // (B, NP, 3)
           const float* __restrict__ poses,   // (B, NG, 7)
           const float* __restrict__ W1, const float* __restrict__ b1,
           const float* __restrict__ g1, const float* __restrict__ be1,
           const float* __restrict__ W2, const float* __restrict__ b2,
           const float* __restrict__ g2, const float* __restrict__ be2,
           const float* __restrict__ W3, const float* __restrict__ b3,
           const float* __restrict__ bscale,
           float* __restrict__ out)            // (B, NH, NG, NP)
{
    extern __shared__ __align__(16) char smraw[];
    Smem& sm = *reinterpret_cast<Smem*>(smraw);

    const int tid = threadIdx.x;

    // ---- Once-per-block prologue (all g-independent) ----
    for (int idx = tid; idx < 8 * 4 * 32; idx += 256) {
        int kb = idx >> 7, rem = idx & 127;
        int nbp = rem >> 5, ln = rem & 31;
        int tt = ln & 3, c = ln >> 2;
        int n0 = (2 * nbp) * 8 + c, n1 = (2 * nbp + 1) * 8 + c;
        int k0 = kb * 16 + 2 * tt;
        float g0 = g1[k0 + 0], g1v = g1[k0 + 1], g8 = g1[k0 + 8], g9 = g1[k0 + 9];
        unsigned x = pack_h2(g0 * W2[(k0 + 0) * 64 + n0], g1v * W2[(k0 + 1) * 64 + n0]);
        unsigned y = pack_h2(g8 * W2[(k0 + 8) * 64 + n0], g9 * W2[(k0 + 9) * 64 + n0]);
        unsigned z = pack_h2(g0 * W2[(k0 + 0) * 64 + n1], g1v * W2[(k0 + 1) * 64 + n1]);
        unsigned w = pack_h2(g8 * W2[(k0 + 8) * 64 + n1], g9 * W2[(k0 + 9) * 64 + n1]);
        sm.Bp[kb][nbp][ln] = make_uint4(x, y, z, w);
    }
    for (int idx = tid; idx < 8 * 32; idx += 256) {
        int kbp = idx >> 5, ln = idx & 31;
        int tt = ln & 3, c = ln >> 2;
        int k0 = 2 * tt, k1 = 2 * tt + 1;
        int n0 = (2 * kbp) * 8 + c, n1 = (2 * kbp + 1) * 8 + c;
        // W1' rows: 0-3 = W1, 4 = b1, 5-7 = 0; single fp16 term
        float w00 = (k0 < 4) ? W1[k0 * 128 + n0] : (k0 == 4 ? b1[n0] : 0.f);
        float w01 = (k1 < 4) ? W1[k1 * 128 + n0] : (k1 == 4 ? b1[n0] : 0.f);
        float w10 = (k0 < 4) ? W1[k0 * 128 + n1] : (k0 == 4 ? b1[n1] : 0.f);
        float w11 = (k1 < 4) ? W1[k1 * 128 + n1] : (k1 == 4 ? b1[n1] : 0.f);
        sm.W1p[kbp][ln] = make_uint2(pack_h2(w00, w01), pack_h2(w10, w11));
    }
    if (tid < 128) {      // stage-D A3 fragments (single fp16 term)
        int kb2 = tid >> 5, ln = tid & 31;
        int tt = ln & 3, gg2 = ln >> 2;
        int k0 = kb2 * 16 + 2 * tt;
        float a0 = g2[k0 + 0] * W3[(k0 + 0) * 8 + gg2];
        float a1 = g2[k0 + 1] * W3[(k0 + 1) * 8 + gg2];
        float a2 = g2[k0 + 8] * W3[(k0 + 8) * 8 + gg2];
        float a3 = g2[k0 + 9] * W3[(k0 + 9) * 8 + gg2];
        sm.bDp[kb2][ln] = make_uint2(pack_h2(a0, a1), pack_h2(a2, a3));
    }
    if (tid >= 128 && tid < 160) {   // G/EB fold vectors, fp32
        int j = tid - 128;
        int nb = j >> 2, tt = j & 3;
        int n0 = nb * 8 + 2 * tt, n1 = n0 + 1;
        float G0 = 0.f, G1 = 0.f, E0 = 0.f, E1 = 0.f;
        #pragma unroll 4
        for (int k = 0; k < 128; ++k) {
            float gk = g1[k], bk = be1[k];
            float w0 = W2[k * 64 + n0], w1 = W2[k * 64 + n1];
            G0 = fmaf(gk, w0, G0); G1 = fmaf(gk, w1, G1);
            E0 = fmaf(bk, w0, E0); E1 = fmaf(bk, w1, E1);
        }
        sm.GEp[nb][tt] = make_float4(G0, G1, E0 + b2[n0], E1 + b2[n1]);
    }
    // Stage first item's scene chunk into buffer 0
    {
        int item0 = blockIdx.x;
        if (item0 < NITEMS && tid < PITEM) {
            int bb = item0 >> 9;
            int p0 = (item0 & 63) << 6;
            const float* spp = scene + ((size_t)bb * NP + p0 + tid) * 3;
            sm.sp[0][tid] = make_float4(spp[0], spp[1], spp[2], 0.f);
        }
    }
    __syncthreads();

    const int wid = tid >> 5, lane = tid & 31;
    const int t = lane & 3, gg = lane >> 2;   // mma fragment coords

    // ---- Per-head fold constants for heads h0 = 2t, h1 = 2t+1 (g-independent) ----
    float K2a = 0.f, K2b = 0.f, K1a = 0.f, K1b = 0.f;
    #pragma unroll 8
    for (int c = 0; c < 64; ++c) {
        float2 w = *reinterpret_cast<const float2*>(W3 + c * 8 + 2 * t);
        float gc = __ldg(g2 + c), bc = __ldg(be2 + c);
        K2a = fmaf(gc, w.x, K2a); K2b = fmaf(gc, w.y, K2b);
        K1a = fmaf(bc, w.x, K1a); K1b = fmaf(bc, w.y, K1b);
    }
    const float bsa = __ldg(bscale + 2 * t), bsb = __ldg(bscale + 2 * t + 1);
    const float C0a = (K1a + __ldg(b3 + 2 * t)) * bsa;
    const float C0b = (K1b + __ldg(b3 + 2 * t + 1)) * bsb;

    // ---- Persistent item loop: static stride schedule ----
    int bufn = 0;
    for (int item = blockIdx.x; item < NITEMS; item += PBLKS, bufn ^= 1) {
        __syncthreads();   // sp[bufn] staged & visible; prev readers of sp[bufn^1] done

        // Prefetch next item's scene chunk into the alternate buffer
        int nxt = item + PBLKS;
        if (nxt < NITEMS && tid < PITEM) {
            int bbn = nxt >> 9;
            int p0n = (nxt & 63) << 6;
            const float* spp = scene + ((size_t)bbn * NP + p0n + tid) * 3;
            sm.sp[bufn ^ 1][tid] = make_float4(spp[0], spp[1], spp[2], 0.f);
        }

        // Decode item
        const int bb = item >> 9;
        const int rem = item & 511;
        const int g = ((rem >> 6) << 3) + wid;
        const int p0 = (rem & 63) << 6;
        const float4* spb = sm.sp[bufn];

        // Pose -> rotation (per item, per warp)
        const float* pp = poses + ((size_t)(bb * NG + g)) * 7;
        float tx = pp[0], ty = pp[1], tz = pp[2];
        float qx = pp[3], qy = pp[4], qz = pp[5], qw = pp[6];
        float inv = 1.f / (sqrtf(qx * qx + qy * qy + qz * qz + qw * qw) + 1e-8f);
        qx *= inv; qy *= inv; qz *= inv; qw *= inv;
        float xx = qx * qx, yy = qy * qy, zz = qz * qz;
        float xy = qx * qy, xz = qx * qz, yz = qy * qz;
        float wx = qw * qx, wy = qw * qy, wz = qw * qz;
        float R00 = 1.f - 2.f * (yy + zz), R01 = 2.f * (xy - wz), R02 = 2.f * (xz + wy);
        float R10 = 2.f * (xy + wz), R11 = 1.f - 2.f * (xx + zz), R12 = 2.f * (yz - wx);
        float R20 = 2.f * (xz - wy), R21 = 2.f * (yz + wx), R22 = 1.f - 2.f * (xx + yy);

        const size_t outbase = (((size_t)bb * NH) * NG + g) * NP + p0;

        #pragma unroll
        for (int itp = 0; itp < 2; ++itp) {   // dual-tile passes: tiles 2itp, 2itp+1
            // ---- Geometry + k8 A-frags for both tiles ----
            unsigned af00, af01, af10, af11;
            #pragma unroll
            for (int u = 0; u < 2; ++u) {
                int base = (2 * itp + u) * TILE;
                float4 PA = spb[base + gg];
                float4 PB = spb[base + gg + 8];
                float rxA = PA.x - tx, ryA = PA.y - ty, rzA = PA.z - tz;
                float lxA = R00 * rxA + R10 * ryA + R20 * rzA;
                float lyA = R01 * rxA + R11 * ryA + R21 * rzA;
                float lzA = R02 * rxA + R12 * ryA + R22 * rzA;
                float ddA = sqrtf(lxA * lxA + lyA * lyA + lzA * lzA);
                float rxB = PB.x - tx, ryB = PB.y - ty, rzB = PB.z - tz;
                float lxB = R00 * rxB + R10 * ryB + R20 * rzB;
                float lyB = R01 * rxB + R11 * ryB + R21 * rzB;
                float lzB = R02 * rxB + R12 * ryB + R22 * rzB;
                float ddB = sqrtf(lxB * lxB + lyB * lyB + lzB * lzB);
                float s0A = (t == 0) ? lxA : (t == 1) ? lzA : (t == 2) ? 1.f : 0.f;
                float s1A = (t == 0) ? lyA : (t == 1) ? ddA : 0.f;
                float s0B = (t == 0) ? lxB : (t == 1) ? lzB : (t == 2) ? 1.f : 0.f;
                float s1B = (t == 0) ? lyB : (t == 1) ? ddB : 0.f;
                if (u == 0) { af00 = pack_h2(s0A, s1A); af01 = pack_h2(s0B, s1B); }
                else        { af10 = pack_h2(s0A, s1A); af11 = pack_h2(s0B, s1B); }
            }

            // ---- Fused B+C over kb: one weight sweep feeds BOTH tiles ----
            float d0[8][4], d1[8][4];
            #pragma unroll
            for (int nb = 0; nb < 8; ++nb) {
                d0[nb][0] = d0[nb][1] = d0[nb][2] = d0[nb][3] = 0.f;
                d1[nb][0] = d1[nb][1] = d1[nb][2] = d1[nb][3] = 0.f;
            }
            float sA0 = 0.f, qA0 = 0.f, sB0 = 0.f, qB0 = 0.f;
            float sA1 = 0.f, qA1 = 0.f, sB1 = 0.f, qB1 = 0.f;

            #pragma unroll
            for (int kb = 0; kb < 8; ++kb) {
                uint2 wb = sm.W1p[kb][lane];
                float e0[4] = {0.f, 0.f, 0.f, 0.f};
                float f0[4] = {0.f, 0.f, 0.f, 0.f};
                float e1[4] = {0.f, 0.f, 0.f, 0.f};
                float f1[4] = {0.f, 0.f, 0.f, 0.f};
                mma_f16_k8(e0, af00, af01, wb.x);   // tile0, n-block 2kb
                mma_f16_k8(f0, af00, af01, wb.y);   // tile0, n-block 2kb+1
                mma_f16_k8(e1, af10, af11, wb.x);   // tile1
                mma_f16_k8(f1, af10, af11, wb.y);
                // relu + stats + pack (tile0)
                float v0 = fmaxf(e0[0], 0.f), v1 = fmaxf(e0[1], 0.f);
                float v2 = fmaxf(e0[2], 0.f), v3 = fmaxf(e0[3], 0.f);
                float v4 = fmaxf(f0[0], 0.f), v5 = fmaxf(f0[1], 0.f);
                float v6 = fmaxf(f0[2], 0.f), v7 = fmaxf(f0[3], 0.f);
                sA0 += (v0 + v1) + (v4 + v5);
                qA0 = fmaf(v0, v0, fmaf(v1, v1, fmaf(v4, v4, fmaf(v5, v5, qA0))));
                sB0 += (v2 + v3) + (v6 + v7);
                qB0 = fmaf(v2, v2, fmaf(v3, v3, fmaf(v6, v6, fmaf(v7, v7, qB0))));
                unsigned a0f[4];
                a0f[0] = pack_h2(v0, v1);
                a0f[1] = pack_h2(v2, v3);
                a0f[2] = pack_h2(v4, v5);
                a0f[3] = pack_h2(v6, v7);
                // relu + stats + pack (tile1)
                float u0 = fmaxf(e1[0], 0.f), u1 = fmaxf(e1[1], 0.f);
                float u2 = fmaxf(e1[2], 0.f), u3 = fmaxf(e1[3], 0.f);
                float u4 = fmaxf(f1[0], 0.f), u5 = fmaxf(f1[1], 0.f);
                float u6 = fmaxf(f1[2], 0.f), u7 = fmaxf(f1[3], 0.f);
                sA1 += (u0 + u1) + (u4 + u5);
                qA1 = fmaf(u0, u0, fmaf(u1, u1, fmaf(u4, u4, fmaf(u5, u5, qA1))));
                sB1 += (u2 + u3) + (u6 + u7);
                qB1 = fmaf(u2, u2, fmaf(u3, u3, fmaf(u6, u6, fmaf(u7, u7, qB1))));
                unsigned a1f[4];
                a1f[0] = pack_h2(u0, u1);
                a1f[1] = pack_h2(u2, u3);
                a1f[2] = pack_h2(u4, u5);
                a1f[3] = pack_h2(u6, u7);
                // stage C: one Bp load serves both tiles
                #pragma unroll
                for (int nbp = 0; nbp < 4; ++nbp) {
                    uint4 bp = sm.Bp[kb][nbp][lane];
                    mma_f16(d0[2 * nbp],     a0f, bp.x, bp.y);
                    mma_f16(d0[2 * nbp + 1], a0f, bp.z, bp.w);
                    mma_f16(d1[2 * nbp],     a1f, bp.x, bp.y);
                    mma_f16(d1[2 * nbp + 1], a1f, bp.z, bp.w);
                }
            }

            // ---- LN1 stats reduce (both tiles together) ----
            #pragma unroll
            for (int o = 1; o <= 2; o <<= 1) {
                sA0 += __shfl_xor_sync(0xffffffffu, sA0, o);
                qA0 += __shfl_xor_sync(0xffffffffu, qA0, o);
                sB0 += __shfl_xor_sync(0xffffffffu, sB0, o);
                qB0 += __shfl_xor_sync(0xffffffffu, qB0, o);
                sA1 += __shfl_xor_sync(0xffffffffu, sA1, o);
                qA1 += __shfl_xor_sync(0xffffffffu, qA1, o);
                sB1 += __shfl_xor_sync(0xffffffffu, sB1, o);
                qB1 += __shfl_xor_sync(0xffffffffu, qB1, o);
            }
            float mu1A0 = sA0 * (1.f / 128.f);
            float rs1A0 = rsqrtf(fmaxf(qA0 * (1.f / 128.f) - mu1A0 * mu1A0, 0.f) + 1e-5f);
            float ng1A0 = -mu1A0 * rs1A0;
            float mu1B0 = sB0 * (1.f / 128.f);
            float rs1B0 = rsqrtf(fmaxf(qB0 * (1.f / 128.f) - mu1B0 * mu1B0, 0.f) + 1e-5f);
            float ng1B0 = -mu1B0 * rs1B0;
            float mu1A1 = sA1 * (1.f / 128.f);
            float rs1A1 = rsqrtf(fmaxf(qA1 * (1.f / 128.f) - mu1A1 * mu1A1, 0.f) + 1e-5f);
            float ng1A1 = -mu1A1 * rs1A1;
            float mu1B1 = sB1 * (1.f / 128.f);
            float rs1B1 = rsqrtf(fmaxf(qB1 * (1.f / 128.f) - mu1B1 * mu1B1, 0.f) + 1e-5f);
            float ng1B1 = -mu1B1 * rs1B1;

            // ---- MERGED epilogue + stage D (single-term A3, fp32 G/EB) ----
            float dh0[4] = {0.f, 0.f, 0.f, 0.f};
            float dh1[4] = {0.f, 0.f, 0.f, 0.f};
            float sg0 = 0.f, qg0 = 0.f, sh0 = 0.f, qh0 = 0.f;
            float sg1 = 0.f, qg1 = 0.f, sh1 = 0.f, qh1 = 0.f;
            #pragma unroll
            for (int kb2 = 0; kb2 < 4; ++kb2) {
                const int nb0 = 2 * kb2, nb1 = 2 * kb2 + 1;
                float4 ge0 = sm.GEp[nb0][t];   // {G0x, G0y, E0x, E0y}
                float4 ge1 = sm.GEp[nb1][t];
                uint2 bd = sm.bDp[kb2][lane];
                // tile0 v's
                float v00 = fmaxf(fmaf(rs1A0, d0[nb0][0], fmaf(ng1A0, ge0.x, ge0.z)), 0.f);
                float v01 = fmaxf(fmaf(rs1A0, d0[nb0][1], fmaf(ng1A0, ge0.y, ge0.w)), 0.f);
                float v10 = fmaxf(fmaf(rs1B0, d0[nb0][2], fmaf(ng1B0, ge0.x, ge0.z)), 0.f);
                float v11 = fmaxf(fmaf(rs1B0, d0[nb0][3], fmaf(ng1B0, ge0.y, ge0.w)), 0.f);
                float v20 = fmaxf(fmaf(rs1A0, d0[nb1][0], fmaf(ng1A0, ge1.x, ge1.z)), 0.f);
                float v21 = fmaxf(fmaf(rs1A0, d0[nb1][1], fmaf(ng1A0, ge1.y, ge1.w)), 0.f);
                float v30 = fmaxf(fmaf(rs1B0, d0[nb1][2], fmaf(ng1B0, ge1.x, ge1.z)), 0.f);
                float v31 = fmaxf(fmaf(rs1B0, d0[nb1][3], fmaf(ng1B0, ge1.y, ge1.w)), 0.f);
                sg0 += (v00 + v01) + (v20 + v21);
                qg0 = fmaf(v00, v00, fmaf(v01, v01, fmaf(v20, v20, fmaf(v21, v21, qg0))));
                sh0 += (v10 + v11) + (v30 + v31);
                qh0 = fmaf(v10, v10, fmaf(v11, v11, fmaf(v30, v30, fmaf(v31, v31, qh0))));
                unsigned av0[4];
                av0[0] = pack_h2(v00, v01);
                av0[1] = pack_h2(v10, v11);
                av0[2] = pack_h2(v20, v21);
                av0[3] = pack_h2(v30, v31);
                // tile1 v's
                float w00 = fmaxf(fmaf(rs1A1, d1[nb0][0], fmaf(ng1A1, ge0.x, ge0.z)), 0.f);
                float w01 = fmaxf(fmaf(rs1A1, d1[nb0][1], fmaf(ng1A1, ge0.y, ge0.w)), 0.f);
                float w10 = fmaxf(fmaf(rs1B1, d1[nb0][2], fmaf(ng1B1, ge0.x, ge0.z)), 0.f);
                float w11 = fmaxf(fmaf(rs1B1, d1[nb0][3], fmaf(ng1B1, ge0.y, ge0.w)), 0.f);
                float w20 = fmaxf(fmaf(rs1A1, d1[nb1][0], fmaf(ng1A1, ge1.x, ge1.z)), 0.f);
                float w21 = fmaxf(fmaf(rs1A1, d1[nb1][1], fmaf(ng1A1, ge1.y, ge1.w)), 0.f);
                float w30 = fmaxf(fmaf(rs1B1, d1[nb1][2], fmaf(ng1B1, ge1.x, ge1.z)), 0.f);
                float w31 = fmaxf(fmaf(rs1B1, d1[nb1][3], fmaf(ng1B1, ge1.y, ge1.w)), 0.f);
                sg1 += (w00 + w01) + (w20 + w21);
                qg1 = fmaf(w00, w00, fmaf(w01, w01, fmaf(w20, w20, fmaf(w21, w21, qg1))));
                sh1 += (w10 + w11) + (w30 + w31);
                qh1 = fmaf(w10, w10, fmaf(w11, w11, fmaf(w30, w30, fmaf(w31, w31, qh1))));
                unsigned av1[4];
                av1[0] = pack_h2(w00, w01);
                av1[1] = pack_h2(w10, w11);
                av1[2] = pack_h2(w20, w21);
                av1[3] = pack_h2(w30, w31);
                // 2 independent chains (single-term A3)
                mma_f16(dh0, av0, bd.x, bd.y);
                mma_f16(dh1, av1, bd.x, bd.y);
            }
            // merged LN2 stats reduce (both tiles)
            #pragma unroll
            for (int o = 1; o <= 2; o <<= 1) {
                sg0 += __shfl_xor_sync(0xffffffffu, sg0, o);
                qg0 += __shfl_xor_sync(0xffffffffu, qg0, o);
                sh0 += __shfl_xor_sync(0xffffffffu, sh0, o);
                qh0 += __shfl_xor_sync(0xffffffffu, qh0, o);
                sg1 += __shfl_xor_sync(0xffffffffu, sg1, o);
                qg1 += __shfl_xor_sync(0xffffffffu, qg1, o);
                sh1 += __shfl_xor_sync(0xffffffffu, sh1, o);
                qh1 += __shfl_xor_sync(0xffffffffu, qh1, o);
            }

            // ---- Outputs, tile0 then tile1 ----
            #pragma unroll
            for (int u = 0; u < 2; ++u) {
                float sg = u ? sg1 : sg0, qg = u ? qg1 : qg0;
                float sh = u ? sh1 : sh0, qh = u ? qh1 : qh0;
                const float* dh = u ? dh1 : dh0;
                float muA = sg * (1.f / 64.f);
                float rsA = rsqrtf(fmaxf(qg * (1.f / 64.f) - muA * muA, 0.f) + 1e-5f);
                float muB = sh * (1.f / 64.f);
                float rsB = rsqrtf(fmaxf(qh * (1.f / 64.f) - muB * muB, 0.f) + 1e-5f);

                const int pw = (2 * itp + u) * TILE;
                float* oA = out + outbase + (size_t)(2 * t) * (NG * NP) + pw;
                float* oB = out + outbase + (size_t)(2 * t + 1) * (NG * NP) + pw;
                float m1 = rsA * bsa, m2 = rsA * bsb;
                float m3 = rsB * bsa, m4 = rsB * bsb;
                oA[gg]     = fmaf(dh[0], m1, fmaf(-muA * m1, K2a, C0a));
                oB[gg]     = fmaf(dh[1], m2, fmaf(-muA * m2, K2b, C0b));
                oA[gg + 8] = fmaf(dh[2], m3, fmaf(-muB * m3, K2a, C0a));
                oB[gg + 8] = fmaf(dh[3], m4, fmaf(-muB * m4, K2b, C0b));
            }
        }
    }
}

extern "C" void kernel_launch(void* const* d_in, const int* in_sizes, int n_in,
                              void* d_out, int out_size) {
    // metadata order: grasp_tokens, scene_points, grasp_poses, W1, b1, g1, beta1,
    //                 W2, b2, g2, beta2, W3, b3, bias_scale
    const float* scene  = (const float*)d_in[1];
    const float* poses  = (const float*)d_in[2];
    const float* W1     = (const float*)d_in[3];
    const float* b1     = (const float*)d_in[4];
    const float* g1     = (const float*)d_in[5];
    const float* be1    = (const float*)d_in[6];
    const float* W2     = (const float*)d_in[7];
    const float* b2     = (const float*)d_in[8];
    const float* g2     = (const float*)d_in[9];
    const float* be2    = (const float*)d_in[10];
    const float* W3     = (const float*)d_in[11];
    const float* b3     = (const float*)d_in[12];
    const float* bscale = (const float*)d_in[13];
    float* out = (float*)d_out;

    cudaFuncSetAttribute(gab_kernel, cudaFuncAttributeMaxDynamicSharedMemorySize,
                         (int)sizeof(Smem));
    gab_kernel<<<PBLKS, 256, sizeof(Smem)>>>(scene, poses, W1, b1, g1, be1,
                                             W2, b2, g2, be2, W3, b3, bscale, out);
}